// round 15
// baseline (speedup 1.0000x reference)
#include <cuda_runtime.h>
#include <cuda_bf16.h>
#include <mma.h>
#include <math.h>

using namespace nvcuda;

constexpr int Bc      = 4;
constexpr int Sc      = 2048;
constexpr int Dc      = 1024;
constexpr int Hc      = 16;
constexpr int DEPTHc  = 64;
constexpr int M_TOT   = Bc * Sc;              // 8192
constexpr long long OUT_ELEMS  = (long long)M_TOT * Dc;
constexpr long long ATTN_ELEMS = (long long)Bc * Hc * Sc * Sc;
constexpr float SCALE = 0.125f;

constexpr size_t ACT_N = (size_t)M_TOT * Dc;
constexpr size_t W_N   = (size_t)Dc * Dc;

// ---- device scratch ----
__device__ __nv_bfloat16 g_wh[4 * W_N],  g_wl[4 * W_N];
__device__ __nv_bfloat16 g_inh[3 * ACT_N], g_inl[3 * ACT_N];
__device__ __nv_bfloat16 g_qh[ACT_N], g_ql[ACT_N];
__device__ __nv_bfloat16 g_kh[ACT_N], g_kl[ACT_N];
__device__ __nv_bfloat16 g_vh[ACT_N], g_vl[ACT_N];
__device__ __nv_bfloat16 g_ctxh[ACT_N], g_ctxl[ACT_N];
__device__ float g_inv[(size_t)Bc * Hc * Sc];
__device__ float g_attn_fb[(size_t)ATTN_ELEMS];

__device__ __forceinline__ void split2(float x, __nv_bfloat16& hi, __nv_bfloat16& lo) {
    hi = __float2bfloat16(x);
    lo = __float2bfloat16(x - __bfloat162float(hi));
}

__device__ __forceinline__ void cpa16(void* smem, const void* gmem) {
    unsigned s = (unsigned)__cvta_generic_to_shared(smem);
    asm volatile("cp.async.cg.shared.global [%0], [%1], 16;\n" :: "r"(s), "l"(gmem));
}
__device__ __forceinline__ void cp_commit() {
    asm volatile("cp.async.commit_group;\n" ::: "memory");
}
template <int N> __device__ __forceinline__ void cp_wait() {
    asm volatile("cp.async.wait_group %0;\n" :: "n"(N) : "memory");
}

typedef wmma::fragment<wmma::matrix_a, 16, 16, 16, __nv_bfloat16, wmma::row_major> FragA;
typedef wmma::fragment<wmma::matrix_b, 16, 16, 16, __nv_bfloat16, wmma::row_major> FragBR;
typedef wmma::fragment<wmma::matrix_b, 16, 16, 16, __nv_bfloat16, wmma::col_major> FragBC;
typedef wmma::fragment<wmma::accumulator, 16, 16, 16, float> FragC;

// ---------------------------------------------------------------------------
// Pre-split kernels
// ---------------------------------------------------------------------------
__global__ __launch_bounds__(256) void presplit_w(
    const float* __restrict__ w0, const float* __restrict__ w1,
    const float* __restrict__ w2, const float* __restrict__ w3,
    __nv_bfloat16* __restrict__ h, __nv_bfloat16* __restrict__ l)
{
    int z = blockIdx.y;
    const float* src = (z == 0) ? w0 : (z == 1) ? w1 : (z == 2) ? w2 : w3;
    size_t off = (size_t)z * W_N;
    size_t i = ((size_t)blockIdx.x * 256 + threadIdx.x) * 8;
    float4 a = *(const float4*)(src + i);
    float4 b = *(const float4*)(src + i + 4);
    __nv_bfloat16 hh[8], ll[8];
    split2(a.x, hh[0], ll[0]); split2(a.y, hh[1], ll[1]);
    split2(a.z, hh[2], ll[2]); split2(a.w, hh[3], ll[3]);
    split2(b.x, hh[4], ll[4]); split2(b.y, hh[5], ll[5]);
    split2(b.z, hh[6], ll[6]); split2(b.w, hh[7], ll[7]);
    *(uint4*)(h + off + i) = *(uint4*)hh;
    *(uint4*)(l + off + i) = *(uint4*)ll;
}

__global__ __launch_bounds__(256) void presplit_in(
    const float* __restrict__ a0, const float* __restrict__ a1,
    const float* __restrict__ a2,
    __nv_bfloat16* __restrict__ h, __nv_bfloat16* __restrict__ l)
{
    int z = blockIdx.y;
    const float* src = (z == 0) ? a0 : (z == 1) ? a1 : a2;
    size_t off = (size_t)z * ACT_N;
    size_t i = ((size_t)blockIdx.x * 256 + threadIdx.x) * 8;
    float4 a = *(const float4*)(src + i);
    float4 b = *(const float4*)(src + i + 4);
    __nv_bfloat16 hh[8], ll[8];
    split2(a.x, hh[0], ll[0]); split2(a.y, hh[1], ll[1]);
    split2(a.z, hh[2], ll[2]); split2(a.w, hh[3], ll[3]);
    split2(b.x, hh[4], ll[4]); split2(b.y, hh[5], ll[5]);
    split2(b.z, hh[6], ll[6]); split2(b.w, hh[7], ll[7]);
    *(uint4*)(h + off + i) = *(uint4*)hh;
    *(uint4*)(l + off + i) = *(uint4*)ll;
}

// ---------------------------------------------------------------------------
// Projection GEMM (pre-split bf16, double-buffered). BM=BN=128, BK=32.
// ---------------------------------------------------------------------------
constexpr int ALD2 = 40;
constexpr int BLD2 = 136;
constexpr int SLD  = 132;

constexpr int SZ_A = 128 * ALD2 * 2;
constexpr int SZ_B = 32 * BLD2 * 2;
constexpr int P_AH0 = 0,            P_AH1 = SZ_A;
constexpr int P_AL0 = 2 * SZ_A,     P_AL1 = 3 * SZ_A;
constexpr int P_B0  = 4 * SZ_A;
constexpr int P_BH0 = P_B0,             P_BH1 = P_B0 + SZ_B;
constexpr int P_BL0 = P_B0 + 2 * SZ_B,  P_BL1 = P_B0 + 3 * SZ_B;
constexpr int SMEM_PROJ = P_B0 + 4 * SZ_B;

__device__ __forceinline__ void proj_core(
    const __nv_bfloat16* __restrict__ Agh, const __nv_bfloat16* __restrict__ Agl,
    const __nv_bfloat16* __restrict__ Wgh, const __nv_bfloat16* __restrict__ Wgl,
    const float* __restrict__ bias,
    float* __restrict__ outf,
    __nv_bfloat16* __restrict__ outh, __nv_bfloat16* __restrict__ outl, int split)
{
    extern __shared__ char sm[];
    __nv_bfloat16* AT[2][2] = {
        {(__nv_bfloat16*)(sm + P_AH0), (__nv_bfloat16*)(sm + P_AH1)},
        {(__nv_bfloat16*)(sm + P_AL0), (__nv_bfloat16*)(sm + P_AL1)}};
    __nv_bfloat16* BT[2][2] = {
        {(__nv_bfloat16*)(sm + P_BH0), (__nv_bfloat16*)(sm + P_BH1)},
        {(__nv_bfloat16*)(sm + P_BL0), (__nv_bfloat16*)(sm + P_BL1)}};

    const int t  = threadIdx.x;
    const int w  = t >> 5;
    const int wm = w >> 2;
    const int wn = w & 3;
    const int m0 = blockIdx.y * 128;
    const int n0 = blockIdx.x * 128;

    FragC acc[4][2];
#pragma unroll
    for (int i = 0; i < 4; i++)
#pragma unroll
        for (int j = 0; j < 2; j++) wmma::fill_fragment(acc[i][j], 0.0f);

    const int ar = t >> 2, ac = (t & 3) * 8;
    const int br = t >> 4, bc = (t & 15) * 8;

#define LOAD_TILE(K0, BUF)                                                         \
    do {                                                                            \
        _Pragma("unroll")                                                           \
        for (int u = 0; u < 2; u++) {                                               \
            int r = ar + u * 64;                                                    \
            *(uint4*)&AT[0][BUF][r * ALD2 + ac] =                                   \
                *(const uint4*)&Agh[(size_t)(m0 + r) * Dc + (K0) + ac];             \
            *(uint4*)&AT[1][BUF][r * ALD2 + ac] =                                   \
                *(const uint4*)&Agl[(size_t)(m0 + r) * Dc + (K0) + ac];             \
            int rb = br + u * 16;                                                   \
            *(uint4*)&BT[0][BUF][rb * BLD2 + bc] =                                  \
                *(const uint4*)&Wgh[(size_t)((K0) + rb) * Dc + n0 + bc];            \
            *(uint4*)&BT[1][BUF][rb * BLD2 + bc] =                                  \
                *(const uint4*)&Wgl[(size_t)((K0) + rb) * Dc + n0 + bc];            \
        }                                                                           \
    } while (0)

    LOAD_TILE(0, 0);
    __syncthreads();

    for (int kt = 0; kt < 32; kt++) {
        int cur = kt & 1;
        if (kt < 31) LOAD_TILE((kt + 1) * 32, cur ^ 1);
#pragma unroll
        for (int ks = 0; ks < 32; ks += 16) {
            FragA ah[4], al[4];
#pragma unroll
            for (int i = 0; i < 4; i++) {
                wmma::load_matrix_sync(ah[i], &AT[0][cur][(wm * 64 + i * 16) * ALD2 + ks], ALD2);
                wmma::load_matrix_sync(al[i], &AT[1][cur][(wm * 64 + i * 16) * ALD2 + ks], ALD2);
            }
#pragma unroll
            for (int j = 0; j < 2; j++) {
                FragBR bh, bl;
                wmma::load_matrix_sync(bh, &BT[0][cur][ks * BLD2 + wn * 32 + j * 16], BLD2);
                wmma::load_matrix_sync(bl, &BT[1][cur][ks * BLD2 + wn * 32 + j * 16], BLD2);
#pragma unroll
                for (int i = 0; i < 4; i++) {
                    wmma::mma_sync(acc[i][j], ah[i], bh, acc[i][j]);
                    wmma::mma_sync(acc[i][j], ah[i], bl, acc[i][j]);
                    wmma::mma_sync(acc[i][j], al[i], bh, acc[i][j]);
                }
            }
        }
        __syncthreads();
    }
#undef LOAD_TILE

    float* Stage = (float*)sm;
#pragma unroll
    for (int i = 0; i < 4; i++)
#pragma unroll
        for (int j = 0; j < 2; j++)
            wmma::store_matrix_sync(&Stage[(wm * 64 + i * 16) * SLD + wn * 32 + j * 16],
                                    acc[i][j], SLD, wmma::mem_row_major);
    __syncthreads();

#pragma unroll
    for (int u = 0; u < 8; u++) {
        int idx = t + u * 256;
        int r = idx >> 4, c = (idx & 15) * 8;
        float4 b0 = *(const float4*)&bias[n0 + c];
        float4 b1 = *(const float4*)&bias[n0 + c + 4];
        const float* sp = &Stage[r * SLD + c];
        float fv[8];
        fv[0] = sp[0] + b0.x; fv[1] = sp[1] + b0.y; fv[2] = sp[2] + b0.z; fv[3] = sp[3] + b0.w;
        fv[4] = sp[4] + b1.x; fv[5] = sp[5] + b1.y; fv[6] = sp[6] + b1.z; fv[7] = sp[7] + b1.w;
        if (split) {
            __nv_bfloat16 hh[8], ll[8];
#pragma unroll
            for (int e = 0; e < 8; e++) split2(fv[e], hh[e], ll[e]);
            int m = m0 + r, n = n0 + c;
            size_t o = (((size_t)((m >> 11) * Hc + (n >> 6))) * Sc + (m & 2047)) * DEPTHc
                       + (n & 63);
            *(uint4*)&outh[o] = *(uint4*)hh;
            *(uint4*)&outl[o] = *(uint4*)ll;
        } else {
            size_t o = (size_t)(m0 + r) * Dc + n0 + c;
            *(float4*)&outf[o]     = make_float4(fv[0], fv[1], fv[2], fv[3]);
            *(float4*)&outf[o + 4] = make_float4(fv[4], fv[5], fv[6], fv[7]);
        }
    }
}

__global__ __launch_bounds__(256, 2) void proj_qkv(
    const __nv_bfloat16* __restrict__ inh, const __nv_bfloat16* __restrict__ inl,
    const __nv_bfloat16* __restrict__ wh,  const __nv_bfloat16* __restrict__ wl,
    const float* __restrict__ bQ, const float* __restrict__ bK, const float* __restrict__ bV,
    __nv_bfloat16* __restrict__ qh, __nv_bfloat16* __restrict__ ql,
    __nv_bfloat16* __restrict__ kh, __nv_bfloat16* __restrict__ kl,
    __nv_bfloat16* __restrict__ vh, __nv_bfloat16* __restrict__ vl)
{
    int z = blockIdx.z;
    const __nv_bfloat16* Agh = inh + (size_t)z * ACT_N;
    const __nv_bfloat16* Agl = inl + (size_t)z * ACT_N;
    const __nv_bfloat16* Wgh = wh + (size_t)z * W_N;
    const __nv_bfloat16* Wgl = wl + (size_t)z * W_N;
    const float* bias = (z == 0) ? bQ : (z == 1) ? bK : bV;
    __nv_bfloat16* oh = (z == 0) ? qh : (z == 1) ? kh : vh;
    __nv_bfloat16* ol = (z == 0) ? ql : (z == 1) ? kl : vl;
    proj_core(Agh, Agl, Wgh, Wgl, bias, nullptr, oh, ol, 1);
}

__global__ __launch_bounds__(256, 2) void proj_o(
    const __nv_bfloat16* __restrict__ ctxh, const __nv_bfloat16* __restrict__ ctxl,
    const __nv_bfloat16* __restrict__ wh,   const __nv_bfloat16* __restrict__ wl,
    const float* __restrict__ bias, float* __restrict__ out)
{
    proj_core(ctxh, ctxl, wh, wl, bias, out, nullptr, nullptr, 0);
}

// ---------------------------------------------------------------------------
// Fused attention: R10 structure (merged mma chains, 2 CTAs/SM) +
// Q fragments hoisted to registers (invariant across all 32 K-tiles).
// ---------------------------------------------------------------------------
constexpr int QLD  = 72;
constexpr int PSLD = 68;
constexpr int SZ_BF = 64 * QLD * 2;                 // 9216

constexpr int OFF_QH  = 0;
constexpr int OFF_QL  = OFF_QH + SZ_BF;
constexpr int OFF_KH0 = OFF_QL + SZ_BF;
constexpr int OFF_KL0 = OFF_KH0 + SZ_BF;
constexpr int OFF_KH1 = OFF_KL0 + SZ_BF;
constexpr int OFF_KL1 = OFF_KH1 + SZ_BF;
constexpr int OFF_VH  = OFF_KL1 + SZ_BF;
constexpr int OFF_VL  = OFF_VH + SZ_BF;
constexpr int OFF_PH  = OFF_VL + SZ_BF;
constexpr int OFF_PL  = OFF_PH + SZ_BF;
constexpr int OFF_PS  = OFF_PL + SZ_BF;
constexpr int OFF_RS  = OFF_PS + 64 * PSLD * 4;
constexpr int OFF_RI  = OFF_RS + 128 * 4;
constexpr int SMEM_ATTN = OFF_RI + 64 * 4;          // 110,336 B -> 2 CTAs/SM

__global__ __launch_bounds__(256) void attn_fused(
    const __nv_bfloat16* __restrict__ qh_g, const __nv_bfloat16* __restrict__ ql_g,
    const __nv_bfloat16* __restrict__ kh_g, const __nv_bfloat16* __restrict__ kl_g,
    const __nv_bfloat16* __restrict__ vh_g, const __nv_bfloat16* __restrict__ vl_g,
    float* __restrict__ attn,
    __nv_bfloat16* __restrict__ ctxh, __nv_bfloat16* __restrict__ ctxl,
    float* __restrict__ invout)
{
    extern __shared__ char smraw[];
    __nv_bfloat16* Qh = (__nv_bfloat16*)(smraw + OFF_QH);
    __nv_bfloat16* Ql = (__nv_bfloat16*)(smraw + OFF_QL);
    __nv_bfloat16* KHB[2] = {(__nv_bfloat16*)(smraw + OFF_KH0), (__nv_bfloat16*)(smraw + OFF_KH1)};
    __nv_bfloat16* KLB[2] = {(__nv_bfloat16*)(smraw + OFF_KL0), (__nv_bfloat16*)(smraw + OFF_KL1)};
    __nv_bfloat16* Vh = (__nv_bfloat16*)(smraw + OFF_VH);
    __nv_bfloat16* Vl = (__nv_bfloat16*)(smraw + OFF_VL);
    __nv_bfloat16* Ph = (__nv_bfloat16*)(smraw + OFF_PH);
    __nv_bfloat16* Pl = (__nv_bfloat16*)(smraw + OFF_PL);
    float* Ps     = (float*)(smraw + OFF_PS);
    float* rs     = (float*)(smraw + OFF_RS);
    float* rowinv = (float*)(smraw + OFF_RI);

    const int t  = threadIdx.x;
    const int w  = t >> 5;
    const int l  = t & 31;
    const int wm = w >> 1;
    const int wn = w & 1;
    const int m0 = blockIdx.x * 64;
    const int bh = blockIdx.y;
    const int bb = bh >> 4, hh = bh & 15;

    const size_t hbase = (size_t)bh * Sc * DEPTHc;
    const int lr8 = t >> 3, lc8 = (t & 7) * 8;

    // prologue: prefetch K tile 0
#pragma unroll
    for (int u = 0; u < 2; u++) {
        int r = lr8 + u * 32;
        size_t g = hbase + (size_t)r * DEPTHc + lc8;
        cpa16(&KHB[0][r * QLD + lc8], &kh_g[g]);
        cpa16(&KLB[0][r * QLD + lc8], &kl_g[g]);
    }
    cp_commit();

    // load Q strip to smem (once)
#pragma unroll
    for (int u = 0; u < 2; u++) {
        int r = lr8 + u * 32;
        size_t g = hbase + (size_t)(m0 + r) * DEPTHc + lc8;
        *(uint4*)&Qh[r * QLD + lc8] = *(const uint4*)&qh_g[g];
        *(uint4*)&Ql[r * QLD + lc8] = *(const uint4*)&ql_g[g];
    }
    __syncthreads();

    // hoist Q fragments into registers: invariant over the whole kt loop
    FragA qf_h[4], qf_l[4];
#pragma unroll
    for (int d = 0; d < 4; d++) {
        wmma::load_matrix_sync(qf_h[d], &Qh[(wm * 16) * QLD + d * 16], QLD);
        wmma::load_matrix_sync(qf_l[d], &Ql[(wm * 16) * QLD + d * 16], QLD);
    }

    FragC accC[2];
#pragma unroll
    for (int j = 0; j < 2; j++) wmma::fill_fragment(accC[j], 0.0f);

    const int prow = wm * 16 + (l >> 1);
    const int pcb  = wn * 32 + (l & 1) * 16;
    float rsum_part = 0.0f;

    for (int kt = 0; kt < 32; kt++) {
        int cur = kt & 1;
        cp_wait<0>();
        __syncthreads();

        // issue V[kt], then K[kt+1]
#pragma unroll
        for (int u = 0; u < 2; u++) {
            int r = lr8 + u * 32;
            size_t g = hbase + (size_t)(kt * 64 + r) * DEPTHc + lc8;
            cpa16(&Vh[r * QLD + lc8], &vh_g[g]);
            cpa16(&Vl[r * QLD + lc8], &vl_g[g]);
        }
        cp_commit();
        if (kt < 31) {
#pragma unroll
            for (int u = 0; u < 2; u++) {
                int r = lr8 + u * 32;
                size_t g = hbase + (size_t)((kt + 1) * 64 + r) * DEPTHc + lc8;
                cpa16(&KHB[cur ^ 1][r * QLD + lc8], &kh_g[g]);
                cpa16(&KLB[cur ^ 1][r * QLD + lc8], &kl_g[g]);
            }
        }
        cp_commit();

        // QK (Q from registers)
        FragC s[2];
#pragma unroll
        for (int j = 0; j < 2; j++) wmma::fill_fragment(s[j], 0.0f);
#pragma unroll
        for (int d0 = 0; d0 < 64; d0 += 16) {
            const int di = d0 >> 4;
#pragma unroll
            for (int j = 0; j < 2; j++) {
                FragBC bhf, blf;
                wmma::load_matrix_sync(bhf, &KHB[cur][(wn * 32 + j * 16) * QLD + d0], QLD);
                wmma::load_matrix_sync(blf, &KLB[cur][(wn * 32 + j * 16) * QLD + d0], QLD);
                wmma::mma_sync(s[j], qf_h[di], bhf, s[j]);
                wmma::mma_sync(s[j], qf_h[di], blf, s[j]);
                wmma::mma_sync(s[j], qf_l[di], bhf, s[j]);
            }
        }
#pragma unroll
        for (int j = 0; j < 2; j++)
#pragma unroll
            for (int e = 0; e < s[j].num_elements; e++)
                s[j].x[e] = __expf(fminf(s[j].x[e] * SCALE, 80.0f));
#pragma unroll
        for (int j = 0; j < 2; j++)
            wmma::store_matrix_sync(&Ps[(wm * 16) * PSLD + wn * 32 + j * 16],
                                    s[j], PSLD, wmma::mem_row_major);
        __syncwarp();

        // per-warp exp phase: rowsum partial, attn write, split into Ph/Pl
        {
            const float* pr = &Ps[prow * PSLD + pcb];
            float pv[16];
#pragma unroll
            for (int j = 0; j < 4; j++) {
                float4 f = *(const float4*)(pr + j * 4);
                pv[j * 4 + 0] = f.x; pv[j * 4 + 1] = f.y;
                pv[j * 4 + 2] = f.z; pv[j * 4 + 3] = f.w;
                rsum_part += f.x + f.y + f.z + f.w;
            }
            float* adst = attn + ((size_t)bh * Sc + m0 + prow) * Sc + kt * 64 + pcb;
#pragma unroll
            for (int j = 0; j < 4; j++)
                *(float4*)(adst + j * 4) =
                    make_float4(pv[j * 4], pv[j * 4 + 1], pv[j * 4 + 2], pv[j * 4 + 3]);
            __nv_bfloat16 h16[16], l16[16];
#pragma unroll
            for (int e = 0; e < 16; e++) split2(pv[e], h16[e], l16[e]);
            *(uint4*)&Ph[prow * QLD + pcb]     = *(uint4*)h16;
            *(uint4*)&Ph[prow * QLD + pcb + 8] = *(uint4*)(h16 + 8);
            *(uint4*)&Pl[prow * QLD + pcb]     = *(uint4*)l16;
            *(uint4*)&Pl[prow * QLD + pcb + 8] = *(uint4*)(l16 + 8);
        }

        cp_wait<1>();
        __syncthreads();

        // ctx += P @ V
#pragma unroll
        for (int ks = 0; ks < 64; ks += 16) {
            FragA ph, pl;
            wmma::load_matrix_sync(ph, &Ph[(wm * 16) * QLD + ks], QLD);
            wmma::load_matrix_sync(pl, &Pl[(wm * 16) * QLD + ks], QLD);
#pragma unroll
            for (int j = 0; j < 2; j++) {
                FragBR vh, vl;
                wmma::load_matrix_sync(vh, &Vh[ks * QLD + wn * 32 + j * 16], QLD);
                wmma::load_matrix_sync(vl, &Vl[ks * QLD + wn * 32 + j * 16], QLD);
                wmma::mma_sync(accC[j], ph, vh, accC[j]);
                wmma::mma_sync(accC[j], ph, vl, accC[j]);
                wmma::mma_sync(accC[j], pl, vh, accC[j]);
            }
        }
    }

    // merge rowsums
    {
        float rp = rsum_part + __shfl_xor_sync(0xffffffffu, rsum_part, 1);
        if ((l & 1) == 0) rs[wn * 64 + prow] = rp;
    }
    // stage unnormalized ctx to Ps
#pragma unroll
    for (int j = 0; j < 2; j++)
        wmma::store_matrix_sync(&Ps[(wm * 16) * PSLD + wn * 32 + j * 16],
                                accC[j], PSLD, wmma::mem_row_major);
    __syncthreads();

    if (t < 64) {
        float iv = 1.0f / (rs[t] + rs[64 + t]);
        rowinv[t] = iv;
        invout[(size_t)bh * Sc + m0 + t] = iv;
    }
    __syncthreads();

    {
        const int cr = t >> 2, cb = (t & 3) * 4;
        float iv = rowinv[cr];
        size_t base = ((size_t)(bb * Sc) + m0 + cr) * Dc + hh * DEPTHc;
#pragma unroll
        for (int j = 0; j < 4; j++) {
            int c = cb + j * 16;
            float4 vv = *(const float4*)&Ps[cr * PSLD + c];
            __nv_bfloat16 sh[4], sl[4];
            split2(vv.x * iv, sh[0], sl[0]); split2(vv.y * iv, sh[1], sl[1]);
            split2(vv.z * iv, sh[2], sl[2]); split2(vv.w * iv, sh[3], sl[3]);
            *(uint2*)&ctxh[base + c] = *(uint2*)sh;
            *(uint2*)&ctxl[base + c] = *(uint2*)sl;
        }
    }
}

// ---------------------------------------------------------------------------
__global__ __launch_bounds__(256) void rescale_attn(
    float* __restrict__ attn, const float* __restrict__ inv)
{
    size_t i = (size_t)blockIdx.x * blockDim.x + threadIdx.x;
    float iv = __ldg(&inv[i >> 9]);
    float4* p = (float4*)attn;
    float4 vv = p[i];
    vv.x *= iv; vv.y *= iv; vv.z *= iv; vv.w *= iv;
    p[i] = vv;
}

// ---------------------------------------------------------------------------
extern "C" void kernel_launch(void* const* d_in, const int* in_sizes, int n_in,
                              void* d_out, int out_size)
{
    const float* Q   = (const float*)d_in[0];
    const float* K   = (const float*)d_in[1];
    const float* V   = (const float*)d_in[2];
    const float* WQw = (const float*)d_in[3];
    const float* WQb = (const float*)d_in[4];
    const float* WKw = (const float*)d_in[5];
    const float* WKb = (const float*)d_in[6];
    const float* WVw = (const float*)d_in[7];
    const float* WVb = (const float*)d_in[8];
    const float* WOw = (const float*)d_in[9];
    const float* WOb = (const float*)d_in[10];
    float* out = (float*)d_out;

    __nv_bfloat16 *wh, *wl, *inh, *inl, *qh, *ql, *kh, *kl, *vh, *vl, *cth, *ctl;
    float *pfb, *pinv;
    cudaGetSymbolAddress((void**)&wh,  g_wh);
    cudaGetSymbolAddress((void**)&wl,  g_wl);
    cudaGetSymbolAddress((void**)&inh, g_inh);
    cudaGetSymbolAddress((void**)&inl, g_inl);
    cudaGetSymbolAddress((void**)&qh,  g_qh);
    cudaGetSymbolAddress((void**)&ql,  g_ql);
    cudaGetSymbolAddress((void**)&kh,  g_kh);
    cudaGetSymbolAddress((void**)&kl,  g_kl);
    cudaGetSymbolAddress((void**)&vh,  g_vh);
    cudaGetSymbolAddress((void**)&vl,  g_vl);
    cudaGetSymbolAddress((void**)&cth, g_ctxh);
    cudaGetSymbolAddress((void**)&ctl, g_ctxl);
    cudaGetSymbolAddress((void**)&pfb,  g_attn_fb);
    cudaGetSymbolAddress((void**)&pinv, g_inv);

    float* attn = ((long long)out_size >= OUT_ELEMS + ATTN_ELEMS)
                      ? out + OUT_ELEMS : pfb;

    static cudaStream_t s2 = nullptr;
    static cudaEvent_t ev1 = nullptr, ev2 = nullptr;
    static int smem_set = 0;
    if (!smem_set) {
        cudaFuncSetAttribute(attn_fused, cudaFuncAttributeMaxDynamicSharedMemorySize,
                             SMEM_ATTN);
        cudaFuncSetAttribute(proj_qkv, cudaFuncAttributeMaxDynamicSharedMemorySize,
                             SMEM_PROJ);
        cudaFuncSetAttribute(proj_o, cudaFuncAttributeMaxDynamicSharedMemorySize,
                             SMEM_PROJ);
        cudaStreamCreateWithFlags(&s2, cudaStreamNonBlocking);
        cudaEventCreateWithFlags(&ev1, cudaEventDisableTiming);
        cudaEventCreateWithFlags(&ev2, cudaEventDisableTiming);
        smem_set = 1;
    }

    dim3 blk(256);
    dim3 gSplW((unsigned)(W_N / 8 / 256), 4);
    dim3 gSplI((unsigned)(ACT_N / 8 / 256), 3);
    dim3 gProjQKV(Dc / 128, M_TOT / 128, 3);
    dim3 gProjO(Dc / 128, M_TOT / 128);
    dim3 gAttn(Sc / 64, Bc * Hc);
    dim3 gResc((unsigned)(ATTN_ELEMS / 4 / 256));

    presplit_w<<<gSplW, blk>>>(WQw, WKw, WVw, WOw, wh, wl);
    presplit_in<<<gSplI, blk>>>(Q, K, V, inh, inl);
    proj_qkv<<<gProjQKV, blk, SMEM_PROJ>>>(inh, inl, wh, wl, WQb, WKb, WVb,
                                           qh, ql, kh, kl, vh, vl);
    attn_fused<<<gAttn, blk, SMEM_ATTN>>>(qh, ql, kh, kl, vh, vl, attn, cth, ctl, pinv);

    // fork: rescale (DRAM-bound) on s2 concurrent with proj_o (compute-bound)
    cudaEventRecord(ev1, 0);
    cudaStreamWaitEvent(s2, ev1, 0);
    rescale_attn<<<gResc, blk, 0, s2>>>(attn, pinv);
    proj_o<<<gProjO, blk, SMEM_PROJ>>>(cth, ctl, wh + 3 * W_N, wl + 3 * W_N, WOb, out);
    cudaEventRecord(ev2, s2);
    cudaStreamWaitEvent(0, ev2, 0);
}

// round 16
// speedup vs baseline: 1.3639x; 1.3639x over previous
#include <cuda_runtime.h>
#include <cuda_bf16.h>
#include <mma.h>
#include <math.h>

using namespace nvcuda;

constexpr int Bc      = 4;
constexpr int Sc      = 2048;
constexpr int Dc      = 1024;
constexpr int Hc      = 16;
constexpr int DEPTHc  = 64;
constexpr int M_TOT   = Bc * Sc;              // 8192
constexpr long long OUT_ELEMS  = (long long)M_TOT * Dc;
constexpr long long ATTN_ELEMS = (long long)Bc * Hc * Sc * Sc;
constexpr float SCALE = 0.125f;

constexpr size_t ACT_N = (size_t)M_TOT * Dc;
constexpr size_t W_N   = (size_t)Dc * Dc;

// ---- device scratch ----
__device__ __nv_bfloat16 g_wh[4 * W_N],  g_wl[4 * W_N];
__device__ __nv_bfloat16 g_inh[3 * ACT_N], g_inl[3 * ACT_N];
__device__ __nv_bfloat16 g_qh[ACT_N], g_ql[ACT_N];
__device__ __nv_bfloat16 g_kh[ACT_N], g_kl[ACT_N];
__device__ __nv_bfloat16 g_vh[ACT_N], g_vl[ACT_N];
__device__ __nv_bfloat16 g_ctxh[ACT_N], g_ctxl[ACT_N];
__device__ float g_inv[(size_t)Bc * Hc * Sc];
__device__ float g_attn_fb[(size_t)ATTN_ELEMS];

__device__ __forceinline__ void split2(float x, __nv_bfloat16& hi, __nv_bfloat16& lo) {
    hi = __float2bfloat16(x);
    lo = __float2bfloat16(x - __bfloat162float(hi));
}

typedef wmma::fragment<wmma::matrix_a, 16, 16, 16, __nv_bfloat16, wmma::row_major> FragA;
typedef wmma::fragment<wmma::matrix_b, 16, 16, 16, __nv_bfloat16, wmma::row_major> FragBR;
typedef wmma::fragment<wmma::matrix_b, 16, 16, 16, __nv_bfloat16, wmma::col_major> FragBC;
typedef wmma::fragment<wmma::accumulator, 16, 16, 16, float> FragC;

// ---------------------------------------------------------------------------
// Pre-split kernels
// ---------------------------------------------------------------------------
__global__ __launch_bounds__(256) void presplit_w(
    const float* __restrict__ w0, const float* __restrict__ w1,
    const float* __restrict__ w2, const float* __restrict__ w3,
    __nv_bfloat16* __restrict__ h, __nv_bfloat16* __restrict__ l)
{
    int z = blockIdx.y;
    const float* src = (z == 0) ? w0 : (z == 1) ? w1 : (z == 2) ? w2 : w3;
    size_t off = (size_t)z * W_N;
    size_t i = ((size_t)blockIdx.x * 256 + threadIdx.x) * 8;
    float4 a = *(const float4*)(src + i);
    float4 b = *(const float4*)(src + i + 4);
    __nv_bfloat16 hh[8], ll[8];
    split2(a.x, hh[0], ll[0]); split2(a.y, hh[1], ll[1]);
    split2(a.z, hh[2], ll[2]); split2(a.w, hh[3], ll[3]);
    split2(b.x, hh[4], ll[4]); split2(b.y, hh[5], ll[5]);
    split2(b.z, hh[6], ll[6]); split2(b.w, hh[7], ll[7]);
    *(uint4*)(h + off + i) = *(uint4*)hh;
    *(uint4*)(l + off + i) = *(uint4*)ll;
}

__global__ __launch_bounds__(256) void presplit_in(
    const float* __restrict__ a0, const float* __restrict__ a1,
    const float* __restrict__ a2,
    __nv_bfloat16* __restrict__ h, __nv_bfloat16* __restrict__ l)
{
    int z = blockIdx.y;
    const float* src = (z == 0) ? a0 : (z == 1) ? a1 : a2;
    size_t off = (size_t)z * ACT_N;
    size_t i = ((size_t)blockIdx.x * 256 + threadIdx.x) * 8;
    float4 a = *(const float4*)(src + i);
    float4 b = *(const float4*)(src + i + 4);
    __nv_bfloat16 hh[8], ll[8];
    split2(a.x, hh[0], ll[0]); split2(a.y, hh[1], ll[1]);
    split2(a.z, hh[2], ll[2]); split2(a.w, hh[3], ll[3]);
    split2(b.x, hh[4], ll[4]); split2(b.y, hh[5], ll[5]);
    split2(b.z, hh[6], ll[6]); split2(b.w, hh[7], ll[7]);
    *(uint4*)(h + off + i) = *(uint4*)hh;
    *(uint4*)(l + off + i) = *(uint4*)ll;
}

// ---------------------------------------------------------------------------
// Projection GEMM: 128 threads, BM=128, BN=64, BK=32, double-buffered.
// 4 warps, warp tile 64x32. 3 CTAs/SM (reg+smem fit by construction).
// ---------------------------------------------------------------------------
constexpr int PALD = 40;    // 32+8 pad (bf16)
constexpr int PBLD = 72;    // 64+8 pad (bf16)
constexpr int PSTLD = 68;   // stage fp32 pad

constexpr int SZ_PA = 128 * PALD * 2;   // 10240 B per (h/l, buf)
constexpr int SZ_PB = 32 * PBLD * 2;    // 4608 B per (h/l, buf)
constexpr int Q_AH0 = 0,             Q_AH1 = SZ_PA;
constexpr int Q_AL0 = 2 * SZ_PA,     Q_AL1 = 3 * SZ_PA;
constexpr int Q_B0  = 4 * SZ_PA;                       // 40960
constexpr int Q_BH0 = Q_B0,              Q_BH1 = Q_B0 + SZ_PB;
constexpr int Q_BL0 = Q_B0 + 2 * SZ_PB,  Q_BL1 = Q_B0 + 3 * SZ_PB;
constexpr int SMEM_PROJ = Q_B0 + 4 * SZ_PB;            // 59392 B
static_assert(128 * PSTLD * 4 <= SMEM_PROJ, "stage fits");

__device__ __forceinline__ void proj_core(
    const __nv_bfloat16* __restrict__ Agh, const __nv_bfloat16* __restrict__ Agl,
    const __nv_bfloat16* __restrict__ Wgh, const __nv_bfloat16* __restrict__ Wgl,
    const float* __restrict__ bias,
    float* __restrict__ outf,
    __nv_bfloat16* __restrict__ outh, __nv_bfloat16* __restrict__ outl, int split)
{
    extern __shared__ char sm[];
    __nv_bfloat16* AT[2][2] = {
        {(__nv_bfloat16*)(sm + Q_AH0), (__nv_bfloat16*)(sm + Q_AH1)},
        {(__nv_bfloat16*)(sm + Q_AL0), (__nv_bfloat16*)(sm + Q_AL1)}};
    __nv_bfloat16* BT[2][2] = {
        {(__nv_bfloat16*)(sm + Q_BH0), (__nv_bfloat16*)(sm + Q_BH1)},
        {(__nv_bfloat16*)(sm + Q_BL0), (__nv_bfloat16*)(sm + Q_BL1)}};

    const int t  = threadIdx.x;
    const int w  = t >> 5;
    const int wm = w >> 1;          // 0..1 : 64-row strip
    const int wn = w & 1;           // 0..1 : 32-col strip
    const int m0 = blockIdx.y * 128;
    const int n0 = blockIdx.x * 64;

    FragC acc[4][2];
#pragma unroll
    for (int i = 0; i < 4; i++)
#pragma unroll
        for (int j = 0; j < 2; j++) wmma::fill_fragment(acc[i][j], 0.0f);

    const int ar = t >> 1, ac = (t & 1) * 16;   // A: 128 rows x 32 cols
    const int br = t >> 2, bc = (t & 3) * 16;   // B: 32 rows x 64 cols

#define LOAD_TILE(K0, BUF)                                                         \
    do {                                                                            \
        _Pragma("unroll")                                                           \
        for (int u = 0; u < 2; u++) {                                               \
            int r = ar + u * 64;                                                    \
            *(uint4*)&AT[0][BUF][r * PALD + ac] =                                   \
                *(const uint4*)&Agh[(size_t)(m0 + r) * Dc + (K0) + ac];             \
            *(uint4*)&AT[0][BUF][r * PALD + ac + 8] =                               \
                *(const uint4*)&Agh[(size_t)(m0 + r) * Dc + (K0) + ac + 8];         \
            *(uint4*)&AT[1][BUF][r * PALD + ac] =                                   \
                *(const uint4*)&Agl[(size_t)(m0 + r) * Dc + (K0) + ac];             \
            *(uint4*)&AT[1][BUF][r * PALD + ac + 8] =                               \
                *(const uint4*)&Agl[(size_t)(m0 + r) * Dc + (K0) + ac + 8];         \
        }                                                                           \
        *(uint4*)&BT[0][BUF][br * PBLD + bc] =                                      \
            *(const uint4*)&Wgh[(size_t)((K0) + br) * Dc + n0 + bc];                \
        *(uint4*)&BT[0][BUF][br * PBLD + bc + 8] =                                  \
            *(const uint4*)&Wgh[(size_t)((K0) + br) * Dc + n0 + bc + 8];            \
        *(uint4*)&BT[1][BUF][br * PBLD + bc] =                                      \
            *(const uint4*)&Wgl[(size_t)((K0) + br) * Dc + n0 + bc];                \
        *(uint4*)&BT[1][BUF][br * PBLD + bc + 8] =                                  \
            *(const uint4*)&Wgl[(size_t)((K0) + br) * Dc + n0 + bc + 8];            \
    } while (0)

    LOAD_TILE(0, 0);
    __syncthreads();

    for (int kt = 0; kt < 32; kt++) {
        int cur = kt & 1;
        if (kt < 31) LOAD_TILE((kt + 1) * 32, cur ^ 1);
#pragma unroll
        for (int ks = 0; ks < 32; ks += 16) {
            FragA ah[4], al[4];
#pragma unroll
            for (int i = 0; i < 4; i++) {
                wmma::load_matrix_sync(ah[i], &AT[0][cur][(wm * 64 + i * 16) * PALD + ks], PALD);
                wmma::load_matrix_sync(al[i], &AT[1][cur][(wm * 64 + i * 16) * PALD + ks], PALD);
            }
#pragma unroll
            for (int j = 0; j < 2; j++) {
                FragBR bh, bl;
                wmma::load_matrix_sync(bh, &BT[0][cur][ks * PBLD + wn * 32 + j * 16], PBLD);
                wmma::load_matrix_sync(bl, &BT[1][cur][ks * PBLD + wn * 32 + j * 16], PBLD);
#pragma unroll
                for (int i = 0; i < 4; i++) {
                    wmma::mma_sync(acc[i][j], ah[i], bh, acc[i][j]);
                    wmma::mma_sync(acc[i][j], ah[i], bl, acc[i][j]);
                    wmma::mma_sync(acc[i][j], al[i], bh, acc[i][j]);
                }
            }
        }
        __syncthreads();
    }
#undef LOAD_TILE

    // epilogue: stage fp32 tile, bias add, write (split bf16 | fp32)
    float* Stage = (float*)sm;
#pragma unroll
    for (int i = 0; i < 4; i++)
#pragma unroll
        for (int j = 0; j < 2; j++)
            wmma::store_matrix_sync(&Stage[(wm * 64 + i * 16) * PSTLD + wn * 32 + j * 16],
                                    acc[i][j], PSTLD, wmma::mem_row_major);
    __syncthreads();

#pragma unroll
    for (int u = 0; u < 8; u++) {
        int idx = t + u * 128;
        int r = idx >> 3, c = (idx & 7) * 8;
        float4 b0 = *(const float4*)&bias[n0 + c];
        float4 b1 = *(const float4*)&bias[n0 + c + 4];
        const float* sp = &Stage[r * PSTLD + c];
        float fv[8];
        fv[0] = sp[0] + b0.x; fv[1] = sp[1] + b0.y; fv[2] = sp[2] + b0.z; fv[3] = sp[3] + b0.w;
        fv[4] = sp[4] + b1.x; fv[5] = sp[5] + b1.y; fv[6] = sp[6] + b1.z; fv[7] = sp[7] + b1.w;
        if (split) {
            __nv_bfloat16 hh[8], ll[8];
#pragma unroll
            for (int e = 0; e < 8; e++) split2(fv[e], hh[e], ll[e]);
            int m = m0 + r, n = n0 + c;
            size_t o = (((size_t)((m >> 11) * Hc + (n >> 6))) * Sc + (m & 2047)) * DEPTHc
                       + (n & 63);
            *(uint4*)&outh[o] = *(uint4*)hh;
            *(uint4*)&outl[o] = *(uint4*)ll;
        } else {
            size_t o = (size_t)(m0 + r) * Dc + n0 + c;
            *(float4*)&outf[o]     = make_float4(fv[0], fv[1], fv[2], fv[3]);
            *(float4*)&outf[o + 4] = make_float4(fv[4], fv[5], fv[6], fv[7]);
        }
    }
}

__global__ __launch_bounds__(128) void proj_qkv(
    const __nv_bfloat16* __restrict__ inh, const __nv_bfloat16* __restrict__ inl,
    const __nv_bfloat16* __restrict__ wh,  const __nv_bfloat16* __restrict__ wl,
    const float* __restrict__ bQ, const float* __restrict__ bK, const float* __restrict__ bV,
    __nv_bfloat16* __restrict__ qh, __nv_bfloat16* __restrict__ ql,
    __nv_bfloat16* __restrict__ kh, __nv_bfloat16* __restrict__ kl,
    __nv_bfloat16* __restrict__ vh, __nv_bfloat16* __restrict__ vl)
{
    int z = blockIdx.z;
    const __nv_bfloat16* Agh = inh + (size_t)z * ACT_N;
    const __nv_bfloat16* Agl = inl + (size_t)z * ACT_N;
    const __nv_bfloat16* Wgh = wh + (size_t)z * W_N;
    const __nv_bfloat16* Wgl = wl + (size_t)z * W_N;
    const float* bias = (z == 0) ? bQ : (z == 1) ? bK : bV;
    __nv_bfloat16* oh = (z == 0) ? qh : (z == 1) ? kh : vh;
    __nv_bfloat16* ol = (z == 0) ? ql : (z == 1) ? kl : vl;
    proj_core(Agh, Agl, Wgh, Wgl, bias, nullptr, oh, ol, 1);
}

__global__ __launch_bounds__(128) void proj_o(
    const __nv_bfloat16* __restrict__ ctxh, const __nv_bfloat16* __restrict__ ctxl,
    const __nv_bfloat16* __restrict__ wh,   const __nv_bfloat16* __restrict__ wl,
    const float* __restrict__ bias, float* __restrict__ out)
{
    proj_core(ctxh, ctxl, wh, wl, bias, out, nullptr, nullptr, 0);
}

// ---------------------------------------------------------------------------
// Fused attention — exact R10 structure (85 regs, 2 CTAs/SM). DO NOT add
// register-resident fragment state here; it breaks the 128-reg budget.
// ---------------------------------------------------------------------------
constexpr int QLD  = 72;
constexpr int PSLD = 68;

constexpr int SZ_BF = 64 * QLD * 2;
constexpr int OFF_QH = 0;
constexpr int OFF_QL = OFF_QH + SZ_BF;
constexpr int OFF_KH = OFF_QL + SZ_BF;
constexpr int OFF_KL = OFF_KH + SZ_BF;
constexpr int OFF_VH = OFF_KL + SZ_BF;
constexpr int OFF_VL = OFF_VH + SZ_BF;
constexpr int OFF_PH = OFF_VL + SZ_BF;
constexpr int OFF_PL = OFF_PH + SZ_BF;
constexpr int OFF_PS = OFF_PL + SZ_BF;
constexpr int OFF_RI = OFF_PS + 64 * PSLD * 4;
constexpr int SMEM_ATTN = OFF_RI + 64 * 4;   // ~91.6 KB -> 2 CTAs/SM

__global__ __launch_bounds__(256) void attn_fused(
    const __nv_bfloat16* __restrict__ qh_g, const __nv_bfloat16* __restrict__ ql_g,
    const __nv_bfloat16* __restrict__ kh_g, const __nv_bfloat16* __restrict__ kl_g,
    const __nv_bfloat16* __restrict__ vh_g, const __nv_bfloat16* __restrict__ vl_g,
    float* __restrict__ attn,
    __nv_bfloat16* __restrict__ ctxh, __nv_bfloat16* __restrict__ ctxl,
    float* __restrict__ invout)
{
    extern __shared__ char smraw[];
    __nv_bfloat16* Qh = (__nv_bfloat16*)(smraw + OFF_QH);
    __nv_bfloat16* Ql = (__nv_bfloat16*)(smraw + OFF_QL);
    __nv_bfloat16* Kh = (__nv_bfloat16*)(smraw + OFF_KH);
    __nv_bfloat16* Kl = (__nv_bfloat16*)(smraw + OFF_KL);
    __nv_bfloat16* Vh = (__nv_bfloat16*)(smraw + OFF_VH);
    __nv_bfloat16* Vl = (__nv_bfloat16*)(smraw + OFF_VL);
    __nv_bfloat16* Ph = (__nv_bfloat16*)(smraw + OFF_PH);
    __nv_bfloat16* Pl = (__nv_bfloat16*)(smraw + OFF_PL);
    float* Ps     = (float*)(smraw + OFF_PS);
    float* rowinv = (float*)(smraw + OFF_RI);

    const int t  = threadIdx.x;
    const int w  = t >> 5;
    const int wm = w >> 1;
    const int wn = w & 1;
    const int m0 = blockIdx.x * 64;
    const int bh = blockIdx.y;
    const int bb = bh >> 4, hh = bh & 15;

    const size_t hbase = (size_t)bh * Sc * DEPTHc;
    const int lr8 = t >> 3, lc8 = (t & 7) * 8;

    // load Q strip 64x64 (bf16 hi/lo, uint4)
#pragma unroll
    for (int u = 0; u < 2; u++) {
        int r = lr8 + u * 32;
        size_t g = hbase + (size_t)(m0 + r) * DEPTHc + lc8;
        *(uint4*)&Qh[r * QLD + lc8] = *(const uint4*)&qh_g[g];
        *(uint4*)&Ql[r * QLD + lc8] = *(const uint4*)&ql_g[g];
    }

    FragC accC[2];
#pragma unroll
    for (int j = 0; j < 2; j++) wmma::fill_fragment(accC[j], 0.0f);
    float rowsum = 0.0f;

    const int cr = t >> 2;
    const int cb = (t & 3) * 4;

    for (int kt = 0; kt < 32; kt++) {
        // load K, V tiles (bf16 hi/lo)
#pragma unroll
        for (int u = 0; u < 2; u++) {
            int r = lr8 + u * 32;
            size_t g = hbase + (size_t)(kt * 64 + r) * DEPTHc + lc8;
            *(uint4*)&Kh[r * QLD + lc8] = *(const uint4*)&kh_g[g];
            *(uint4*)&Kl[r * QLD + lc8] = *(const uint4*)&kl_g[g];
            *(uint4*)&Vh[r * QLD + lc8] = *(const uint4*)&vh_g[g];
            *(uint4*)&Vl[r * QLD + lc8] = *(const uint4*)&vl_g[g];
        }
        __syncthreads();

        // scores
        FragC s[2];
#pragma unroll
        for (int j = 0; j < 2; j++) wmma::fill_fragment(s[j], 0.0f);
#pragma unroll
        for (int d0 = 0; d0 < 64; d0 += 16) {
            FragA ah, al;
            wmma::load_matrix_sync(ah, &Qh[(wm * 16) * QLD + d0], QLD);
            wmma::load_matrix_sync(al, &Ql[(wm * 16) * QLD + d0], QLD);
#pragma unroll
            for (int j = 0; j < 2; j++) {
                FragBC bhf, blf;
                wmma::load_matrix_sync(bhf, &Kh[(wn * 32 + j * 16) * QLD + d0], QLD);
                wmma::load_matrix_sync(blf, &Kl[(wn * 32 + j * 16) * QLD + d0], QLD);
                wmma::mma_sync(s[j], ah, bhf, s[j]);
                wmma::mma_sync(s[j], ah, blf, s[j]);
                wmma::mma_sync(s[j], al, bhf, s[j]);
            }
        }
#pragma unroll
        for (int j = 0; j < 2; j++)
            wmma::store_matrix_sync(&Ps[(wm * 16) * PSLD + wn * 32 + j * 16],
                                    s[j], PSLD, wmma::mem_row_major);
        __syncthreads();

        // p = exp(scale*s): write unnormalized attn, split into Ph/Pl
        {
            float* adst = attn + ((size_t)bh * Sc + m0 + cr) * Sc + kt * 64;
            float lsum = 0.0f;
#pragma unroll
            for (int j = 0; j < 4; j++) {
                int c = cb + j * 16;
                float4 sv = *(const float4*)&Ps[cr * PSLD + c];
                float4 pv;
                pv.x = __expf(fminf(sv.x * SCALE, 80.0f));
                pv.y = __expf(fminf(sv.y * SCALE, 80.0f));
                pv.z = __expf(fminf(sv.z * SCALE, 80.0f));
                pv.w = __expf(fminf(sv.w * SCALE, 80.0f));
                lsum += pv.x + pv.y + pv.z + pv.w;
                *(float4*)(adst + c) = pv;
                int o = cr * QLD + c;
                split2(pv.x, Ph[o + 0], Pl[o + 0]); split2(pv.y, Ph[o + 1], Pl[o + 1]);
                split2(pv.z, Ph[o + 2], Pl[o + 2]); split2(pv.w, Ph[o + 3], Pl[o + 3]);
            }
            rowsum += lsum;
        }
        __syncthreads();

        // ctx += P @ V
#pragma unroll
        for (int ks = 0; ks < 64; ks += 16) {
            FragA ph, pl;
            wmma::load_matrix_sync(ph, &Ph[(wm * 16) * QLD + ks], QLD);
            wmma::load_matrix_sync(pl, &Pl[(wm * 16) * QLD + ks], QLD);
#pragma unroll
            for (int j = 0; j < 2; j++) {
                FragBR vh, vl;
                wmma::load_matrix_sync(vh, &Vh[ks * QLD + wn * 32 + j * 16], QLD);
                wmma::load_matrix_sync(vl, &Vl[ks * QLD + wn * 32 + j * 16], QLD);
                wmma::mma_sync(accC[j], ph, vh, accC[j]);
                wmma::mma_sync(accC[j], ph, vl, accC[j]);
                wmma::mma_sync(accC[j], pl, vh, accC[j]);
            }
        }
        __syncthreads();
    }

    // rowsum merge across the 4 threads owning each row
    {
        float rs = rowsum;
        rs += __shfl_xor_sync(0xffffffffu, rs, 1);
        rs += __shfl_xor_sync(0xffffffffu, rs, 2);
        float iv = 1.0f / rs;
        if ((t & 3) == 0) {
            rowinv[cr] = iv;
            invout[(size_t)bh * Sc + m0 + cr] = iv;
        }
    }
    __syncthreads();

    // write ctx normalized, split to bf16 hi/lo, merged-head layout
#pragma unroll
    for (int j = 0; j < 2; j++)
        wmma::store_matrix_sync(&Ps[(wm * 16) * PSLD + wn * 32 + j * 16],
                                accC[j], PSLD, wmma::mem_row_major);
    __syncthreads();
    {
        float iv = rowinv[cr];
        size_t base = ((size_t)(bb * Sc) + m0 + cr) * Dc + hh * DEPTHc;
#pragma unroll
        for (int j = 0; j < 4; j++) {
            int c = cb + j * 16;
            float4 vv = *(const float4*)&Ps[cr * PSLD + c];
            __nv_bfloat16 sh[4], sl[4];
            split2(vv.x * iv, sh[0], sl[0]); split2(vv.y * iv, sh[1], sl[1]);
            split2(vv.z * iv, sh[2], sl[2]); split2(vv.w * iv, sh[3], sl[3]);
            *(uint2*)&ctxh[base + c] = *(uint2*)sh;
            *(uint2*)&ctxl[base + c] = *(uint2*)sl;
        }
    }
}

// ---------------------------------------------------------------------------
__global__ __launch_bounds__(256) void rescale_attn(
    float* __restrict__ attn, const float* __restrict__ inv)
{
    size_t i = (size_t)blockIdx.x * blockDim.x + threadIdx.x;
    float iv = __ldg(&inv[i >> 9]);
    float4* p = (float4*)attn;
    float4 vv = p[i];
    vv.x *= iv; vv.y *= iv; vv.z *= iv; vv.w *= iv;
    p[i] = vv;
}

// ---------------------------------------------------------------------------
extern "C" void kernel_launch(void* const* d_in, const int* in_sizes, int n_in,
                              void* d_out, int out_size)
{
    const float* Q   = (const float*)d_in[0];
    const float* K   = (const float*)d_in[1];
    const float* V   = (const float*)d_in[2];
    const float* WQw = (const float*)d_in[3];
    const float* WQb = (const float*)d_in[4];
    const float* WKw = (const float*)d_in[5];
    const float* WKb = (const float*)d_in[6];
    const float* WVw = (const float*)d_in[7];
    const float* WVb = (const float*)d_in[8];
    const float* WOw = (const float*)d_in[9];
    const float* WOb = (const float*)d_in[10];
    float* out = (float*)d_out;

    __nv_bfloat16 *wh, *wl, *inh, *inl, *qh, *ql, *kh, *kl, *vh, *vl, *cth, *ctl;
    float *pfb, *pinv;
    cudaGetSymbolAddress((void**)&wh,  g_wh);
    cudaGetSymbolAddress((void**)&wl,  g_wl);
    cudaGetSymbolAddress((void**)&inh, g_inh);
    cudaGetSymbolAddress((void**)&inl, g_inl);
    cudaGetSymbolAddress((void**)&qh,  g_qh);
    cudaGetSymbolAddress((void**)&ql,  g_ql);
    cudaGetSymbolAddress((void**)&kh,  g_kh);
    cudaGetSymbolAddress((void**)&kl,  g_kl);
    cudaGetSymbolAddress((void**)&vh,  g_vh);
    cudaGetSymbolAddress((void**)&vl,  g_vl);
    cudaGetSymbolAddress((void**)&cth, g_ctxh);
    cudaGetSymbolAddress((void**)&ctl, g_ctxl);
    cudaGetSymbolAddress((void**)&pfb,  g_attn_fb);
    cudaGetSymbolAddress((void**)&pinv, g_inv);

    float* attn = ((long long)out_size >= OUT_ELEMS + ATTN_ELEMS)
                      ? out + OUT_ELEMS : pfb;

    static cudaStream_t s2 = nullptr;
    static cudaEvent_t ev1 = nullptr, ev2 = nullptr;
    static int smem_set = 0;
    if (!smem_set) {
        cudaFuncSetAttribute(attn_fused, cudaFuncAttributeMaxDynamicSharedMemorySize,
                             SMEM_ATTN);
        cudaFuncSetAttribute(proj_qkv, cudaFuncAttributeMaxDynamicSharedMemorySize,
                             SMEM_PROJ);
        cudaFuncSetAttribute(proj_o, cudaFuncAttributeMaxDynamicSharedMemorySize,
                             SMEM_PROJ);
        cudaStreamCreateWithFlags(&s2, cudaStreamNonBlocking);
        cudaEventCreateWithFlags(&ev1, cudaEventDisableTiming);
        cudaEventCreateWithFlags(&ev2, cudaEventDisableTiming);
        smem_set = 1;
    }

    dim3 blk(256);
    dim3 blkP(128);
    dim3 gSplW((unsigned)(W_N / 8 / 256), 4);
    dim3 gSplI((unsigned)(ACT_N / 8 / 256), 3);
    dim3 gProjQKV(Dc / 64, M_TOT / 128, 3);      // 16 x 64 x 3
    dim3 gProjO(Dc / 64, M_TOT / 128);           // 16 x 64
    dim3 gAttn(Sc / 64, Bc * Hc);                // 32 x 64
    dim3 gResc((unsigned)(ATTN_ELEMS / 4 / 256));

    presplit_w<<<gSplW, blk>>>(WQw, WKw, WVw, WOw, wh, wl);
    presplit_in<<<gSplI, blk>>>(Q, K, V, inh, inl);
    proj_qkv<<<gProjQKV, blkP, SMEM_PROJ>>>(inh, inl, wh, wl, WQb, WKb, WVb,
                                            qh, ql, kh, kl, vh, vl);
    attn_fused<<<gAttn, blk, SMEM_ATTN>>>(qh, ql, kh, kl, vh, vl, attn, cth, ctl, pinv);

    // fork: rescale (DRAM-bound) on s2 concurrent with proj_o (compute-bound)
    cudaEventRecord(ev1, 0);
    cudaStreamWaitEvent(s2, ev1, 0);
    rescale_attn<<<gResc, blk, 0, s2>>>(attn, pinv);
    proj_o<<<gProjO, blkP, SMEM_PROJ>>>(cth, ctl, wh + 3 * W_N, wl + 3 * W_N, WOb, out);
    cudaEventRecord(ev2, s2);
    cudaStreamWaitEvent(0, ev2, 0);
}

// round 17
// speedup vs baseline: 1.5269x; 1.1195x over previous
#include <cuda_runtime.h>
#include <cuda_bf16.h>
#include <mma.h>
#include <math.h>

using namespace nvcuda;

constexpr int Bc      = 4;
constexpr int Sc      = 2048;
constexpr int Dc      = 1024;
constexpr int Hc      = 16;
constexpr int DEPTHc  = 64;
constexpr int M_TOT   = Bc * Sc;              // 8192
constexpr long long OUT_ELEMS  = (long long)M_TOT * Dc;
constexpr long long ATTN_ELEMS = (long long)Bc * Hc * Sc * Sc;
constexpr float SCALE = 0.125f;

constexpr size_t ACT_N = (size_t)M_TOT * Dc;
constexpr size_t W_N   = (size_t)Dc * Dc;

// ---- device scratch ----
__device__ __nv_bfloat16 g_wh[4 * W_N],  g_wl[4 * W_N];
__device__ __nv_bfloat16 g_inh[3 * ACT_N], g_inl[3 * ACT_N];
__device__ __nv_bfloat16 g_qh[ACT_N], g_ql[ACT_N];
__device__ __nv_bfloat16 g_kh[ACT_N], g_kl[ACT_N];
__device__ __nv_bfloat16 g_vh[ACT_N], g_vl[ACT_N];
__device__ __nv_bfloat16 g_ctxh[ACT_N], g_ctxl[ACT_N];
__device__ float g_inv[(size_t)Bc * Hc * Sc];
__device__ float g_attn_fb[(size_t)ATTN_ELEMS];

__device__ __forceinline__ void split2(float x, __nv_bfloat16& hi, __nv_bfloat16& lo) {
    hi = __float2bfloat16(x);
    lo = __float2bfloat16(x - __bfloat162float(hi));
}

__device__ __forceinline__ void cpa16(void* smem, const void* gmem) {
    unsigned s = (unsigned)__cvta_generic_to_shared(smem);
    asm volatile("cp.async.cg.shared.global [%0], [%1], 16;\n" :: "r"(s), "l"(gmem));
}
__device__ __forceinline__ void cp_commit() {
    asm volatile("cp.async.commit_group;\n" ::: "memory");
}
template <int N> __device__ __forceinline__ void cp_wait() {
    asm volatile("cp.async.wait_group %0;\n" :: "n"(N) : "memory");
}

typedef wmma::fragment<wmma::matrix_a, 16, 16, 16, __nv_bfloat16, wmma::row_major> FragA;
typedef wmma::fragment<wmma::matrix_b, 16, 16, 16, __nv_bfloat16, wmma::row_major> FragBR;
typedef wmma::fragment<wmma::matrix_b, 16, 16, 16, __nv_bfloat16, wmma::col_major> FragBC;
typedef wmma::fragment<wmma::accumulator, 16, 16, 16, float> FragC;

// ---------------------------------------------------------------------------
// Pre-split kernels
// ---------------------------------------------------------------------------
__global__ __launch_bounds__(256) void presplit_w(
    const float* __restrict__ w0, const float* __restrict__ w1,
    const float* __restrict__ w2, const float* __restrict__ w3,
    __nv_bfloat16* __restrict__ h, __nv_bfloat16* __restrict__ l)
{
    int z = blockIdx.y;
    const float* src = (z == 0) ? w0 : (z == 1) ? w1 : (z == 2) ? w2 : w3;
    size_t off = (size_t)z * W_N;
    size_t i = ((size_t)blockIdx.x * 256 + threadIdx.x) * 8;
    float4 a = *(const float4*)(src + i);
    float4 b = *(const float4*)(src + i + 4);
    __nv_bfloat16 hh[8], ll[8];
    split2(a.x, hh[0], ll[0]); split2(a.y, hh[1], ll[1]);
    split2(a.z, hh[2], ll[2]); split2(a.w, hh[3], ll[3]);
    split2(b.x, hh[4], ll[4]); split2(b.y, hh[5], ll[5]);
    split2(b.z, hh[6], ll[6]); split2(b.w, hh[7], ll[7]);
    *(uint4*)(h + off + i) = *(uint4*)hh;
    *(uint4*)(l + off + i) = *(uint4*)ll;
}

__global__ __launch_bounds__(256) void presplit_in(
    const float* __restrict__ a0, const float* __restrict__ a1,
    const float* __restrict__ a2,
    __nv_bfloat16* __restrict__ h, __nv_bfloat16* __restrict__ l)
{
    int z = blockIdx.y;
    const float* src = (z == 0) ? a0 : (z == 1) ? a1 : a2;
    size_t off = (size_t)z * ACT_N;
    size_t i = ((size_t)blockIdx.x * 256 + threadIdx.x) * 8;
    float4 a = *(const float4*)(src + i);
    float4 b = *(const float4*)(src + i + 4);
    __nv_bfloat16 hh[8], ll[8];
    split2(a.x, hh[0], ll[0]); split2(a.y, hh[1], ll[1]);
    split2(a.z, hh[2], ll[2]); split2(a.w, hh[3], ll[3]);
    split2(b.x, hh[4], ll[4]); split2(b.y, hh[5], ll[5]);
    split2(b.z, hh[6], ll[6]); split2(b.w, hh[7], ll[7]);
    *(uint4*)(h + off + i) = *(uint4*)hh;
    *(uint4*)(l + off + i) = *(uint4*)ll;
}

// ---------------------------------------------------------------------------
// Projection GEMM: 256 threads, BM=BN=128, BK=32 (R10 geometry), but loads
// go through cp.async (no register staging) to cut reg pressure -> 2 CTAs/SM.
// ---------------------------------------------------------------------------
constexpr int ALD2 = 40;
constexpr int BLD2 = 136;
constexpr int SLD  = 132;

constexpr int SZ_A = 128 * ALD2 * 2;   // 10240 B
constexpr int SZ_B = 32 * BLD2 * 2;    // 8704 B
constexpr int P_AH0 = 0,            P_AH1 = SZ_A;
constexpr int P_AL0 = 2 * SZ_A,     P_AL1 = 3 * SZ_A;
constexpr int P_B0  = 4 * SZ_A;
constexpr int P_BH0 = P_B0,             P_BH1 = P_B0 + SZ_B;
constexpr int P_BL0 = P_B0 + 2 * SZ_B,  P_BL1 = P_B0 + 3 * SZ_B;
constexpr int SMEM_PROJ = P_B0 + 4 * SZ_B;   // 75776 B; x2 CTAs = 151.5 KB OK

__device__ __forceinline__ void proj_core(
    const __nv_bfloat16* __restrict__ Agh, const __nv_bfloat16* __restrict__ Agl,
    const __nv_bfloat16* __restrict__ Wgh, const __nv_bfloat16* __restrict__ Wgl,
    const float* __restrict__ bias,
    float* __restrict__ outf,
    __nv_bfloat16* __restrict__ outh, __nv_bfloat16* __restrict__ outl, int split)
{
    extern __shared__ char sm[];
    __nv_bfloat16* AT[2][2] = {
        {(__nv_bfloat16*)(sm + P_AH0), (__nv_bfloat16*)(sm + P_AH1)},
        {(__nv_bfloat16*)(sm + P_AL0), (__nv_bfloat16*)(sm + P_AL1)}};
    __nv_bfloat16* BT[2][2] = {
        {(__nv_bfloat16*)(sm + P_BH0), (__nv_bfloat16*)(sm + P_BH1)},
        {(__nv_bfloat16*)(sm + P_BL0), (__nv_bfloat16*)(sm + P_BL1)}};

    const int t  = threadIdx.x;
    const int w  = t >> 5;
    const int wm = w >> 2;
    const int wn = w & 3;
    const int m0 = blockIdx.y * 128;
    const int n0 = blockIdx.x * 128;

    FragC acc[4][2];
#pragma unroll
    for (int i = 0; i < 4; i++)
#pragma unroll
        for (int j = 0; j < 2; j++) wmma::fill_fragment(acc[i][j], 0.0f);

    const int ar = t >> 2, ac = (t & 3) * 8;     // A: 64 rows x 4 cols(x8), rows ar, ar+64
    const int br = t >> 4, bc = (t & 15) * 8;    // B: 16 rows x 16 cols(x8), rows br, br+16

#define LOAD_TILE_ASYNC(K0, BUF)                                                   \
    do {                                                                            \
        _Pragma("unroll")                                                           \
        for (int u = 0; u < 2; u++) {                                               \
            int r = ar + u * 64;                                                    \
            cpa16(&AT[0][BUF][r * ALD2 + ac],                                       \
                  &Agh[(size_t)(m0 + r) * Dc + (K0) + ac]);                         \
            cpa16(&AT[1][BUF][r * ALD2 + ac],                                       \
                  &Agl[(size_t)(m0 + r) * Dc + (K0) + ac]);                         \
            int rb = br + u * 16;                                                   \
            cpa16(&BT[0][BUF][rb * BLD2 + bc],                                      \
                  &Wgh[(size_t)((K0) + rb) * Dc + n0 + bc]);                        \
            cpa16(&BT[1][BUF][rb * BLD2 + bc],                                      \
                  &Wgl[(size_t)((K0) + rb) * Dc + n0 + bc]);                        \
        }                                                                           \
    } while (0)

    LOAD_TILE_ASYNC(0, 0);
    cp_commit();

    for (int kt = 0; kt < 32; kt++) {
        int cur = kt & 1;
        cp_wait<0>();        // tile kt resident
        __syncthreads();     // all threads see tile kt; prior-iter reads of buf cur^1 done
        if (kt < 31) {
            LOAD_TILE_ASYNC((kt + 1) * 32, cur ^ 1);
            cp_commit();
        }
#pragma unroll
        for (int ks = 0; ks < 32; ks += 16) {
            FragA ah[4], al[4];
#pragma unroll
            for (int i = 0; i < 4; i++) {
                wmma::load_matrix_sync(ah[i], &AT[0][cur][(wm * 64 + i * 16) * ALD2 + ks], ALD2);
                wmma::load_matrix_sync(al[i], &AT[1][cur][(wm * 64 + i * 16) * ALD2 + ks], ALD2);
            }
#pragma unroll
            for (int j = 0; j < 2; j++) {
                FragBR bh, bl;
                wmma::load_matrix_sync(bh, &BT[0][cur][ks * BLD2 + wn * 32 + j * 16], BLD2);
                wmma::load_matrix_sync(bl, &BT[1][cur][ks * BLD2 + wn * 32 + j * 16], BLD2);
#pragma unroll
                for (int i = 0; i < 4; i++) {
                    wmma::mma_sync(acc[i][j], ah[i], bh, acc[i][j]);
                    wmma::mma_sync(acc[i][j], ah[i], bl, acc[i][j]);
                    wmma::mma_sync(acc[i][j], al[i], bh, acc[i][j]);
                }
            }
        }
    }
#undef LOAD_TILE_ASYNC

    __syncthreads();
    float* Stage = (float*)sm;
#pragma unroll
    for (int i = 0; i < 4; i++)
#pragma unroll
        for (int j = 0; j < 2; j++)
            wmma::store_matrix_sync(&Stage[(wm * 64 + i * 16) * SLD + wn * 32 + j * 16],
                                    acc[i][j], SLD, wmma::mem_row_major);
    __syncthreads();

#pragma unroll
    for (int u = 0; u < 8; u++) {
        int idx = t + u * 256;
        int r = idx >> 4, c = (idx & 15) * 8;
        float4 b0 = *(const float4*)&bias[n0 + c];
        float4 b1 = *(const float4*)&bias[n0 + c + 4];
        const float* sp = &Stage[r * SLD + c];
        float fv[8];
        fv[0] = sp[0] + b0.x; fv[1] = sp[1] + b0.y; fv[2] = sp[2] + b0.z; fv[3] = sp[3] + b0.w;
        fv[4] = sp[4] + b1.x; fv[5] = sp[5] + b1.y; fv[6] = sp[6] + b1.z; fv[7] = sp[7] + b1.w;
        if (split) {
            __nv_bfloat16 hh[8], ll[8];
#pragma unroll
            for (int e = 0; e < 8; e++) split2(fv[e], hh[e], ll[e]);
            int m = m0 + r, n = n0 + c;
            size_t o = (((size_t)((m >> 11) * Hc + (n >> 6))) * Sc + (m & 2047)) * DEPTHc
                       + (n & 63);
            *(uint4*)&outh[o] = *(uint4*)hh;
            *(uint4*)&outl[o] = *(uint4*)ll;
        } else {
            size_t o = (size_t)(m0 + r) * Dc + n0 + c;
            *(float4*)&outf[o]     = make_float4(fv[0], fv[1], fv[2], fv[3]);
            *(float4*)&outf[o + 4] = make_float4(fv[4], fv[5], fv[6], fv[7]);
        }
    }
}

__global__ __launch_bounds__(256, 2) void proj_qkv(
    const __nv_bfloat16* __restrict__ inh, const __nv_bfloat16* __restrict__ inl,
    const __nv_bfloat16* __restrict__ wh,  const __nv_bfloat16* __restrict__ wl,
    const float* __restrict__ bQ, const float* __restrict__ bK, const float* __restrict__ bV,
    __nv_bfloat16* __restrict__ qh, __nv_bfloat16* __restrict__ ql,
    __nv_bfloat16* __restrict__ kh, __nv_bfloat16* __restrict__ kl,
    __nv_bfloat16* __restrict__ vh, __nv_bfloat16* __restrict__ vl)
{
    int z = blockIdx.z;
    const __nv_bfloat16* Agh = inh + (size_t)z * ACT_N;
    const __nv_bfloat16* Agl = inl + (size_t)z * ACT_N;
    const __nv_bfloat16* Wgh = wh + (size_t)z * W_N;
    const __nv_bfloat16* Wgl = wl + (size_t)z * W_N;
    const float* bias = (z == 0) ? bQ : (z == 1) ? bK : bV;
    __nv_bfloat16* oh = (z == 0) ? qh : (z == 1) ? kh : vh;
    __nv_bfloat16* ol = (z == 0) ? ql : (z == 1) ? kl : vl;
    proj_core(Agh, Agl, Wgh, Wgl, bias, nullptr, oh, ol, 1);
}

__global__ __launch_bounds__(256, 2) void proj_o(
    const __nv_bfloat16* __restrict__ ctxh, const __nv_bfloat16* __restrict__ ctxl,
    const __nv_bfloat16* __restrict__ wh,   const __nv_bfloat16* __restrict__ wl,
    const float* __restrict__ bias, float* __restrict__ out)
{
    proj_core(ctxh, ctxl, wh, wl, bias, out, nullptr, nullptr, 0);
}

// ---------------------------------------------------------------------------
// Fused attention — exact R10 structure (85-98 regs, 2 CTAs/SM). DO NOT add
// register-resident fragment state here; it breaks the 128-reg budget.
// ---------------------------------------------------------------------------
constexpr int QLD  = 72;
constexpr int PSLD = 68;

constexpr int SZ_BF = 64 * QLD * 2;
constexpr int OFF_QH = 0;
constexpr int OFF_QL = OFF_QH + SZ_BF;
constexpr int OFF_KH = OFF_QL + SZ_BF;
constexpr int OFF_KL = OFF_KH + SZ_BF;
constexpr int OFF_VH = OFF_KL + SZ_BF;
constexpr int OFF_VL = OFF_VH + SZ_BF;
constexpr int OFF_PH = OFF_VL + SZ_BF;
constexpr int OFF_PL = OFF_PH + SZ_BF;
constexpr int OFF_PS = OFF_PL + SZ_BF;
constexpr int OFF_RI = OFF_PS + 64 * PSLD * 4;
constexpr int SMEM_ATTN = OFF_RI + 64 * 4;   // ~91.6 KB -> 2 CTAs/SM

__global__ __launch_bounds__(256) void attn_fused(
    const __nv_bfloat16* __restrict__ qh_g, const __nv_bfloat16* __restrict__ ql_g,
    const __nv_bfloat16* __restrict__ kh_g, const __nv_bfloat16* __restrict__ kl_g,
    const __nv_bfloat16* __restrict__ vh_g, const __nv_bfloat16* __restrict__ vl_g,
    float* __restrict__ attn,
    __nv_bfloat16* __restrict__ ctxh, __nv_bfloat16* __restrict__ ctxl,
    float* __restrict__ invout)
{
    extern __shared__ char smraw[];
    __nv_bfloat16* Qh = (__nv_bfloat16*)(smraw + OFF_QH);
    __nv_bfloat16* Ql = (__nv_bfloat16*)(smraw + OFF_QL);
    __nv_bfloat16* Kh = (__nv_bfloat16*)(smraw + OFF_KH);
    __nv_bfloat16* Kl = (__nv_bfloat16*)(smraw + OFF_KL);
    __nv_bfloat16* Vh = (__nv_bfloat16*)(smraw + OFF_VH);
    __nv_bfloat16* Vl = (__nv_bfloat16*)(smraw + OFF_VL);
    __nv_bfloat16* Ph = (__nv_bfloat16*)(smraw + OFF_PH);
    __nv_bfloat16* Pl = (__nv_bfloat16*)(smraw + OFF_PL);
    float* Ps     = (float*)(smraw + OFF_PS);
    float* rowinv = (float*)(smraw + OFF_RI);

    const int t  = threadIdx.x;
    const int w  = t >> 5;
    const int wm = w >> 1;
    const int wn = w & 1;
    const int m0 = blockIdx.x * 64;
    const int bh = blockIdx.y;
    const int bb = bh >> 4, hh = bh & 15;

    const size_t hbase = (size_t)bh * Sc * DEPTHc;
    const int lr8 = t >> 3, lc8 = (t & 7) * 8;

    // load Q strip 64x64 (bf16 hi/lo, uint4)
#pragma unroll
    for (int u = 0; u < 2; u++) {
        int r = lr8 + u * 32;
        size_t g = hbase + (size_t)(m0 + r) * DEPTHc + lc8;
        *(uint4*)&Qh[r * QLD + lc8] = *(const uint4*)&qh_g[g];
        *(uint4*)&Ql[r * QLD + lc8] = *(const uint4*)&ql_g[g];
    }

    FragC accC[2];
#pragma unroll
    for (int j = 0; j < 2; j++) wmma::fill_fragment(accC[j], 0.0f);
    float rowsum = 0.0f;

    const int cr = t >> 2;
    const int cb = (t & 3) * 4;

    for (int kt = 0; kt < 32; kt++) {
        // load K, V tiles (bf16 hi/lo)
#pragma unroll
        for (int u = 0; u < 2; u++) {
            int r = lr8 + u * 32;
            size_t g = hbase + (size_t)(kt * 64 + r) * DEPTHc + lc8;
            *(uint4*)&Kh[r * QLD + lc8] = *(const uint4*)&kh_g[g];
            *(uint4*)&Kl[r * QLD + lc8] = *(const uint4*)&kl_g[g];
            *(uint4*)&Vh[r * QLD + lc8] = *(const uint4*)&vh_g[g];
            *(uint4*)&Vl[r * QLD + lc8] = *(const uint4*)&vl_g[g];
        }
        __syncthreads();

        // scores
        FragC s[2];
#pragma unroll
        for (int j = 0; j < 2; j++) wmma::fill_fragment(s[j], 0.0f);
#pragma unroll
        for (int d0 = 0; d0 < 64; d0 += 16) {
            FragA ah, al;
            wmma::load_matrix_sync(ah, &Qh[(wm * 16) * QLD + d0], QLD);
            wmma::load_matrix_sync(al, &Ql[(wm * 16) * QLD + d0], QLD);
#pragma unroll
            for (int j = 0; j < 2; j++) {
                FragBC bhf, blf;
                wmma::load_matrix_sync(bhf, &Kh[(wn * 32 + j * 16) * QLD + d0], QLD);
                wmma::load_matrix_sync(blf, &Kl[(wn * 32 + j * 16) * QLD + d0], QLD);
                wmma::mma_sync(s[j], ah, bhf, s[j]);
                wmma::mma_sync(s[j], ah, blf, s[j]);
                wmma::mma_sync(s[j], al, bhf, s[j]);
            }
        }
#pragma unroll
        for (int j = 0; j < 2; j++)
            wmma::store_matrix_sync(&Ps[(wm * 16) * PSLD + wn * 32 + j * 16],
                                    s[j], PSLD, wmma::mem_row_major);
        __syncthreads();

        // p = exp(scale*s): write unnormalized attn, split into Ph/Pl
        {
            float* adst = attn + ((size_t)bh * Sc + m0 + cr) * Sc + kt * 64;
            float lsum = 0.0f;
#pragma unroll
            for (int j = 0; j < 4; j++) {
                int c = cb + j * 16;
                float4 sv = *(const float4*)&Ps[cr * PSLD + c];
                float4 pv;
                pv.x = __expf(fminf(sv.x * SCALE, 80.0f));
                pv.y = __expf(fminf(sv.y * SCALE, 80.0f));
                pv.z = __expf(fminf(sv.z * SCALE, 80.0f));
                pv.w = __expf(fminf(sv.w * SCALE, 80.0f));
                lsum += pv.x + pv.y + pv.z + pv.w;
                *(float4*)(adst + c) = pv;
                int o = cr * QLD + c;
                split2(pv.x, Ph[o + 0], Pl[o + 0]); split2(pv.y, Ph[o + 1], Pl[o + 1]);
                split2(pv.z, Ph[o + 2], Pl[o + 2]); split2(pv.w, Ph[o + 3], Pl[o + 3]);
            }
            rowsum += lsum;
        }
        __syncthreads();

        // ctx += P @ V
#pragma unroll
        for (int ks = 0; ks < 64; ks += 16) {
            FragA ph, pl;
            wmma::load_matrix_sync(ph, &Ph[(wm * 16) * QLD + ks], QLD);
            wmma::load_matrix_sync(pl, &Pl[(wm * 16) * QLD + ks], QLD);
#pragma unroll
            for (int j = 0; j < 2; j++) {
                FragBR vh, vl;
                wmma::load_matrix_sync(vh, &Vh[ks * QLD + wn * 32 + j * 16], QLD);
                wmma::load_matrix_sync(vl, &Vl[ks * QLD + wn * 32 + j * 16], QLD);
                wmma::mma_sync(accC[j], ph, vh, accC[j]);
                wmma::mma_sync(accC[j], ph, vl, accC[j]);
                wmma::mma_sync(accC[j], pl, vh, accC[j]);
            }
        }
        __syncthreads();
    }

    // rowsum merge across the 4 threads owning each row
    {
        float rs = rowsum;
        rs += __shfl_xor_sync(0xffffffffu, rs, 1);
        rs += __shfl_xor_sync(0xffffffffu, rs, 2);
        float iv = 1.0f / rs;
        if ((t & 3) == 0) {
            rowinv[cr] = iv;
            invout[(size_t)bh * Sc + m0 + cr] = iv;
        }
    }
    __syncthreads();

    // write ctx normalized, split to bf16 hi/lo, merged-head layout
#pragma unroll
    for (int j = 0; j < 2; j++)
        wmma::store_matrix_sync(&Ps[(wm * 16) * PSLD + wn * 32 + j * 16],
                                accC[j], PSLD, wmma::mem_row_major);
    __syncthreads();
    {
        float iv = rowinv[cr];
        size_t base = ((size_t)(bb * Sc) + m0 + cr) * Dc + hh * DEPTHc;
#pragma unroll
        for (int j = 0; j < 4; j++) {
            int c = cb + j * 16;
            float4 vv = *(const float4*)&Ps[cr * PSLD + c];
            __nv_bfloat16 sh[4], sl[4];
            split2(vv.x * iv, sh[0], sl[0]); split2(vv.y * iv, sh[1], sl[1]);
            split2(vv.z * iv, sh[2], sl[2]); split2(vv.w * iv, sh[3], sl[3]);
            *(uint2*)&ctxh[base + c] = *(uint2*)sh;
            *(uint2*)&ctxl[base + c] = *(uint2*)sl;
        }
    }
}

// ---------------------------------------------------------------------------
__global__ __launch_bounds__(256) void rescale_attn(
    float* __restrict__ attn, const float* __restrict__ inv)
{
    size_t i = (size_t)blockIdx.x * blockDim.x + threadIdx.x;
    float iv = __ldg(&inv[i >> 9]);
    float4* p = (float4*)attn;
    float4 vv = p[i];
    vv.x *= iv; vv.y *= iv; vv.z *= iv; vv.w *= iv;
    p[i] = vv;
}

// ---------------------------------------------------------------------------
extern "C" void kernel_launch(void* const* d_in, const int* in_sizes, int n_in,
                              void* d_out, int out_size)
{
    const float* Q   = (const float*)d_in[0];
    const float* K   = (const float*)d_in[1];
    const float* V   = (const float*)d_in[2];
    const float* WQw = (const float*)d_in[3];
    const float* WQb = (const float*)d_in[4];
    const float* WKw = (const float*)d_in[5];
    const float* WKb = (const float*)d_in[6];
    const float* WVw = (const float*)d_in[7];
    const float* WVb = (const float*)d_in[8];
    const float* WOw = (const float*)d_in[9];
    const float* WOb = (const float*)d_in[10];
    float* out = (float*)d_out;

    __nv_bfloat16 *wh, *wl, *inh, *inl, *qh, *ql, *kh, *kl, *vh, *vl, *cth, *ctl;
    float *pfb, *pinv;
    cudaGetSymbolAddress((void**)&wh,  g_wh);
    cudaGetSymbolAddress((void**)&wl,  g_wl);
    cudaGetSymbolAddress((void**)&inh, g_inh);
    cudaGetSymbolAddress((void**)&inl, g_inl);
    cudaGetSymbolAddress((void**)&qh,  g_qh);
    cudaGetSymbolAddress((void**)&ql,  g_ql);
    cudaGetSymbolAddress((void**)&kh,  g_kh);
    cudaGetSymbolAddress((void**)&kl,  g_kl);
    cudaGetSymbolAddress((void**)&vh,  g_vh);
    cudaGetSymbolAddress((void**)&vl,  g_vl);
    cudaGetSymbolAddress((void**)&cth, g_ctxh);
    cudaGetSymbolAddress((void**)&ctl, g_ctxl);
    cudaGetSymbolAddress((void**)&pfb,  g_attn_fb);
    cudaGetSymbolAddress((void**)&pinv, g_inv);

    float* attn = ((long long)out_size >= OUT_ELEMS + ATTN_ELEMS)
                      ? out + OUT_ELEMS : pfb;

    static cudaStream_t s2 = nullptr;
    static cudaEvent_t ev1 = nullptr, ev2 = nullptr;
    static int smem_set = 0;
    if (!smem_set) {
        cudaFuncSetAttribute(attn_fused, cudaFuncAttributeMaxDynamicSharedMemorySize,
                             SMEM_ATTN);
        cudaFuncSetAttribute(proj_qkv, cudaFuncAttributeMaxDynamicSharedMemorySize,
                             SMEM_PROJ);
        cudaFuncSetAttribute(proj_o, cudaFuncAttributeMaxDynamicSharedMemorySize,
                             SMEM_PROJ);
        cudaStreamCreateWithFlags(&s2, cudaStreamNonBlocking);
        cudaEventCreateWithFlags(&ev1, cudaEventDisableTiming);
        cudaEventCreateWithFlags(&ev2, cudaEventDisableTiming);
        smem_set = 1;
    }

    dim3 blk(256);
    dim3 gSplW((unsigned)(W_N / 8 / 256), 4);
    dim3 gSplI((unsigned)(ACT_N / 8 / 256), 3);
    dim3 gProjQKV(Dc / 128, M_TOT / 128, 3);     // 8 x 64 x 3
    dim3 gProjO(Dc / 128, M_TOT / 128);          // 8 x 64
    dim3 gAttn(Sc / 64, Bc * Hc);                // 32 x 64
    dim3 gResc((unsigned)(ATTN_ELEMS / 4 / 256));

    presplit_w<<<gSplW, blk>>>(WQw, WKw, WVw, WOw, wh, wl);
    presplit_in<<<gSplI, blk>>>(Q, K, V, inh, inl);
    proj_qkv<<<gProjQKV, blk, SMEM_PROJ>>>(inh, inl, wh, wl, WQb, WKb, WVb,
                                           qh, ql, kh, kl, vh, vl);
    attn_fused<<<gAttn, blk, SMEM_ATTN>>>(qh, ql, kh, kl, vh, vl, attn, cth, ctl, pinv);

    // fork: rescale (DRAM-bound) on s2 concurrent with proj_o (compute-bound)
    cudaEventRecord(ev1, 0);
    cudaStreamWaitEvent(s2, ev1, 0);
    rescale_attn<<<gResc, blk, 0, s2>>>(attn, pinv);
    proj_o<<<gProjO, blk, SMEM_PROJ>>>(cth, ctl, wh + 3 * W_N, wl + 3 * W_N, WOb, out);
    cudaEventRecord(ev2, s2);
    cudaStreamWaitEvent(0, ev2, 0);
}